// round 15
// baseline (speedup 1.0000x reference)
#include <cuda_runtime.h>
#include <cuda_bf16.h>
#include <cstdint>

// MaxUnpooling2D scatter-add: R11 phased structure, but zeroing done by the
// TMA engine (cp.async.bulk shared->global) so it consumes ZERO per-lane
// LSU/L1tex wavefronts -- the resource the scatter is bound on.
// updates: [16,128,128,64] f32   d_in[0]
// mask:    [16,128,128,64] int32 d_in[1], values in [0, 1<<22)
// out:     [16,256,256,64] f32   (256 MB)

static constexpr int OUT_FLAT      = 1 << 22;    // floats per batch
static constexpr int GRP_PER_BATCH = 1 << 18;    // float4-groups per batch
static constexpr int NPHASE        = 5;
static constexpr int CHUNK_BYTES   = 32768;      // smem buffer + TMA chunk
__host__ __device__ constexpr int phase_start(int p)   { return (p == 0) ? 0 : (1 << (p - 1)); }
__host__ __device__ constexpr int phase_batches(int p) { return (p == 0) ? 1 : (1 << (p - 1)); }

// Zero `nchunks` x 32KB starting at dst, via TMA bulk stores.
__global__ __launch_bounds__(256)
void zero_tma(char* __restrict__ dst, unsigned nchunks) {
    extern __shared__ char sbuf[];               // 32KB, zeroed once
    // Cooperative smem zero (2048 x 16B)
    float4 zv = make_float4(0.f, 0.f, 0.f, 0.f);
    #pragma unroll
    for (int j = 0; j < (CHUNK_BYTES / 16) / 256; j++)
        ((float4*)sbuf)[j * 256 + threadIdx.x] = zv;
    __syncthreads();
    // Order generic-proxy STS before async-proxy TMA reads.
    asm volatile("fence.proxy.async.shared::cta;" ::: "memory");

    if (threadIdx.x == 0) {
        uint32_t saddr;
        asm("{ .reg .u64 t; cvta.to.shared.u64 t, %1; cvt.u32.u64 %0, t; }"
            : "=r"(saddr) : "l"(sbuf));
        for (unsigned c = blockIdx.x; c < nchunks; c += gridDim.x) {
            char* g = dst + (size_t)c * CHUNK_BYTES;
            asm volatile(
                "cp.async.bulk.global.shared::cta.bulk_group [%0], [%1], %2;"
                :: "l"(g), "r"(saddr), "r"((unsigned)CHUNK_BYTES) : "memory");
        }
        asm volatile("cp.async.bulk.commit_group;" ::: "memory");
        asm volatile("cp.async.bulk.wait_group 0;" ::: "memory");
    }
    __syncthreads();
}

// Scatter: one float4-group (4 spread REDG) per thread.
__global__ __launch_bounds__(256)
void scatter_phase(const float4* __restrict__ up,
                   const int4*   __restrict__ mk,
                   float*        __restrict__ out,
                   unsigned base) {
    unsigned g = base + blockIdx.x * 256u + threadIdx.x;
    float* outb = out + ((size_t)(g >> 18) << 22);   // per-batch window
    float4 u = up[g];
    int4   m = mk[g];
    atomicAdd(outb + m.x, u.x);
    atomicAdd(outb + m.y, u.y);
    atomicAdd(outb + m.z, u.z);
    atomicAdd(outb + m.w, u.w);
}

extern "C" void kernel_launch(void* const* d_in, const int* in_sizes, int n_in,
                              void* d_out, int out_size) {
    const float4* up  = (const float4*)d_in[0];
    const int4*   mk  = (const int4*)d_in[1];
    float*        out = (float*)d_out;

    // Exactly ONE extra stream (allocation-guard budget), default priority
    // (hi-prio caused inversion in R12).
    cudaStream_t sZ;
    cudaStreamCreateWithFlags(&sZ, cudaStreamNonBlocking);

    cudaEvent_t evFork;
    cudaEventCreateWithFlags(&evFork, cudaEventDisableTiming);
    cudaEventRecord(evFork, 0);
    cudaStreamWaitEvent(sZ, evFork, 0);

    // Side stream: TMA-zero each phase window, event per window.
    cudaEvent_t evZ[NPHASE];
    for (int p = 0; p < NPHASE; p++) {
        char* w = (char*)(out + (size_t)phase_start(p) * OUT_FLAT);
        unsigned bytes   = (unsigned)phase_batches(p) * (OUT_FLAT * 4u);
        unsigned nchunks = bytes / CHUNK_BYTES;      // 512 per batch
        unsigned grid    = nchunks < 256u ? nchunks : 256u;
        zero_tma<<<grid, 256, CHUNK_BYTES, sZ>>>(w, nchunks);
        cudaEventCreateWithFlags(&evZ[p], cudaEventDisableTiming);
        cudaEventRecord(evZ[p], sZ);
    }

    // Origin stream: scatter each phase once its window is zeroed.
    for (int p = 0; p < NPHASE; p++) {
        cudaStreamWaitEvent(0, evZ[p], 0);
        unsigned base   = (unsigned)phase_start(p) * GRP_PER_BATCH;
        unsigned groups = (unsigned)phase_batches(p) * GRP_PER_BATCH;
        scatter_phase<<<groups / 256, 256>>>(up, mk, out, base);
    }
    // Waiting on evZ[4] above also joined sZ back into the origin stream.
}